// round 6
// baseline (speedup 1.0000x reference)
#include <cuda_runtime.h>

#define BB 2
#define SS 2048
#define DM 4096
#define NH 32
#define HD 128
#define QL 12
#define KL 4
#define NT (BB*SS)   // 4096 tokens

typedef unsigned long long u64;

// ---------------- f32x2 packed-math helpers (sm_103a) ----------------------
__device__ __forceinline__ u64 f2pack(float lo, float hi) {
    u64 r; asm("mov.b64 %0, {%1, %2};" : "=l"(r) : "f"(lo), "f"(hi)); return r;
}
__device__ __forceinline__ void f2unpack(u64 v, float& lo, float& hi) {
    asm("mov.b64 {%0, %1}, %2;" : "=f"(lo), "=f"(hi) : "l"(v));
}
__device__ __forceinline__ u64 f2fma(u64 a, u64 b, u64 c) {
    u64 d; asm("fma.rn.f32x2 %0, %1, %2, %3;" : "=l"(d) : "l"(a), "l"(b), "l"(c)); return d;
}
__device__ __forceinline__ u64 f2mul(u64 a, u64 b) {
    u64 d; asm("mul.rn.f32x2 %0, %1, %2;" : "=l"(d) : "l"(a), "l"(b)); return d;
}
__device__ __forceinline__ u64 f2add(u64 a, u64 b) {
    u64 d; asm("add.rn.f32x2 %0, %1, %2;" : "=l"(d) : "l"(a), "l"(b)); return d;
}
__device__ __forceinline__ float ex2f(float x) {
    float y; asm("ex2.approx.f32 %0, %1;" : "=f"(y) : "f"(x)); return y;
}

// ---------------- scratch (device globals; no allocations) ----------------
__device__ __align__(16) float g_Ckv[NT*KL];        // 64 KB
__device__ __align__(16) float g_q  [NT*NH*KL];     // 2 MB  (pre-scaled by 0.5*log2e)
__device__ __align__(16) float g_A  [NT*NH*KL];     // 2 MB
__device__ __align__(16) float g_MP [NH*KL*DM];     // 2 MB  (cols 0,1 of each quad, dup)
__device__ __align__(16) float g_MQ [NH*KL*DM];     // 2 MB  (cols 2,3 of each quad, dup)
__device__ __align__(16) float g_Mb [NH*DM];        // 512 KB

#define QSCALE 0.7213475204444817f   /* 0.5 * log2(e) */

// ============ Kernel 1: x -> C_q, C_kv, q (known-good) ======================
__global__ __launch_bounds__(512) void proj_kernel(
    const float* __restrict__ x,   const float* __restrict__ Wq,
    const float* __restrict__ bq,  const float* __restrict__ Wqk,
    const float* __restrict__ bqk, const float* __restrict__ Wkv,
    const float* __restrict__ bkv)
{
    __shared__ __align__(16) float xs[32][128];
    __shared__ __align__(16) float ws[16][132];
    __shared__ float cq[32][16];

    const int tid  = threadIdx.x;
    const int tok0 = blockIdx.x * 32;
    const int tok  = tid >> 4;
    const int c    = tid & 15;

    u64 acc2 = 0ull;
    for (int d0 = 0; d0 < DM; d0 += 128) {
        #pragma unroll
        for (int i = tid; i < 32*128; i += 512) {
            int t = i >> 7, d = i & 127;
            xs[t][d] = x[(size_t)(tok0 + t)*DM + d0 + d];
        }
        #pragma unroll
        for (int i = tid; i < 16*128; i += 512) {
            int d = i >> 4, cc = i & 15;
            ws[cc][d] = (cc < QL) ? Wq[(size_t)(d0+d)*QL + cc]
                                  : Wkv[(size_t)(d0+d)*KL + (cc-QL)];
        }
        __syncthreads();
        #pragma unroll 8
        for (int d = 0; d < 128; d += 4) {
            ulonglong2 xv = *(const ulonglong2*)&xs[tok][d];
            ulonglong2 wv = *(const ulonglong2*)&ws[c][d];
            acc2 = f2fma(xv.x, wv.x, acc2);
            acc2 = f2fma(xv.y, wv.y, acc2);
        }
        __syncthreads();
    }
    float alo, ahi; f2unpack(acc2, alo, ahi);
    float biased = (alo + ahi) + ((c < QL) ? bq[c] : bkv[c - QL]);
    cq[tok][c] = biased;
    if (c >= QL) g_Ckv[(size_t)(tok0 + tok)*KL + (c - QL)] = biased;
    __syncthreads();

    float cql[QL];
    #pragma unroll
    for (int i = 0; i < QL; ++i) cql[i] = cq[tok][i];
    const int o0 = c * 8;
    #pragma unroll
    for (int oo = 0; oo < 8; ++oo) {
        int o = o0 + oo;
        float s = bqk[o];
        #pragma unroll
        for (int i = 0; i < QL; ++i) s = fmaf(cql[i], Wqk[i*(NH*KL) + o], s);
        g_q[(size_t)(tok0 + tok)*(NH*KL) + o] = QSCALE * s;
    }
}

// ============ Kernel 2: fold Wv_u into Wo, store DUPLICATED P/Q layout ======
// For each column quad {c0,c1,c2,c3}: P = {c0,c0,c1,c1}, Q = {c2,c2,c3,c3}.
__global__ __launch_bounds__(256) void precM_kernel(
    const float* __restrict__ Wvu, const float* __restrict__ Wo,
    const float* __restrict__ bvu)
{
    __shared__ float vu[KL][HD];
    __shared__ float bvs[HD];
    const int h = blockIdx.y;
    const int j = blockIdx.x * 256 + threadIdx.x;
    for (int i = threadIdx.x; i < KL*HD; i += 256) {
        int k = i >> 7, d = i & 127;
        vu[k][d] = Wvu[(size_t)k*(NH*HD) + h*HD + d];
    }
    if (threadIdx.x < HD) bvs[threadIdx.x] = bvu[h*HD + threadIdx.x];
    __syncthreads();

    float a0=0.f, a1=0.f, a2=0.f, a3=0.f, ab=0.f;
    #pragma unroll 4
    for (int d = 0; d < HD; ++d) {
        float w = Wo[(size_t)(h*HD + d)*DM + j];
        a0 = fmaf(vu[0][d], w, a0);
        a1 = fmaf(vu[1][d], w, a1);
        a2 = fmaf(vu[2][d], w, a2);
        a3 = fmaf(vu[3][d], w, a3);
        ab = fmaf(bvs[d],   w, ab);
    }
    // duplicated-interleaved store
    const int r = j & 3;
    const int base = (j & ~3) + ((j & 1) << 1);
    float* dst = (r < 2) ? g_MP : g_MQ;
    float2 v;
    v.x = a0; v.y = a0; *(float2*)&dst[(size_t)(h*KL + 0)*DM + base] = v;
    v.x = a1; v.y = a1; *(float2*)&dst[(size_t)(h*KL + 1)*DM + base] = v;
    v.x = a2; v.y = a2; *(float2*)&dst[(size_t)(h*KL + 2)*DM + base] = v;
    v.x = a3; v.y = a3; *(float2*)&dst[(size_t)(h*KL + 3)*DM + base] = v;
    g_Mb[(size_t)h*DM + j] = ab;
}

// ============ Kernel 3: latent attention (round-5 known-good) ===============
__global__ __launch_bounds__(128) void attn_kernel()
{
    __shared__ __align__(16) float ckx[SS];
    __shared__ __align__(16) float cky[SS];
    __shared__ __align__(16) float ckz[SS];
    __shared__ __align__(16) float ckw[SS];
    const int b = blockIdx.z, h = blockIdx.y;
    const float4* ckv = (const float4*)(g_Ckv + (size_t)b*SS*KL);
    for (int i = threadIdx.x; i < SS; i += 128) {
        float4 v = ckv[i];
        ckx[i] = v.x; cky[i] = v.y; ckz[i] = v.z; ckw[i] = v.w;
    }
    __syncthreads();

    const int tok = b*SS + blockIdx.x*128 + threadIdx.x;
    const float4 qv = *(const float4*)(g_q + (size_t)tok*(NH*KL) + h*KL);
    const u64 qx2 = f2pack(qv.x, qv.x);
    const u64 qy2 = f2pack(qv.y, qv.y);
    const u64 qz2 = f2pack(qv.z, qv.z);
    const u64 qw2 = f2pack(qv.w, qv.w);

    const ulonglong2* cxp = (const ulonglong2*)ckx;
    const ulonglong2* cyp = (const ulonglong2*)cky;
    const ulonglong2* czp = (const ulonglong2*)ckz;
    const ulonglong2* cwp = (const ulonglong2*)ckw;

    u64 lA=0ull, axA=0ull, ayA=0ull, azA=0ull, awA=0ull;
    u64 lB=0ull, axB=0ull, ayB=0ull, azB=0ull, awB=0ull;
    #pragma unroll 4
    for (int k = 0; k < SS/4; ++k) {
        ulonglong2 cx2 = cxp[k], cy2 = cyp[k], cz2 = czp[k], cw2 = cwp[k];
        u64 sa = f2mul(qx2, cx2.x);
        u64 sb = f2mul(qx2, cx2.y);
        sa = f2fma(qy2, cy2.x, sa);  sb = f2fma(qy2, cy2.y, sb);
        sa = f2fma(qz2, cz2.x, sa);  sb = f2fma(qz2, cz2.y, sb);
        sa = f2fma(qw2, cw2.x, sa);  sb = f2fma(qw2, cw2.y, sb);
        float s0,s1,s2,s3; f2unpack(sa, s0, s1); f2unpack(sb, s2, s3);
        u64 ea = f2pack(ex2f(s0), ex2f(s1));
        u64 eb = f2pack(ex2f(s2), ex2f(s3));
        lA  = f2add(lA, ea);             lB  = f2add(lB, eb);
        axA = f2fma(ea, cx2.x, axA);     axB = f2fma(eb, cx2.y, axB);
        ayA = f2fma(ea, cy2.x, ayA);     ayB = f2fma(eb, cy2.y, ayB);
        azA = f2fma(ea, cz2.x, azA);     azB = f2fma(eb, cz2.y, azB);
        awA = f2fma(ea, cw2.x, awA);     awB = f2fma(eb, cw2.y, awB);
    }
    u64 l2  = f2add(lA, lB);
    u64 ax2 = f2add(axA, axB), ay2 = f2add(ayA, ayB);
    u64 az2 = f2add(azA, azB), aw2 = f2add(awA, awB);
    float l0,l1,x0,x1,y0,y1,z0,z1,w0,w1;
    f2unpack(l2, l0, l1);
    f2unpack(ax2, x0, x1); f2unpack(ay2, y0, y1);
    f2unpack(az2, z0, z1); f2unpack(aw2, w0, w1);
    float inv = 1.f / (l0 + l1);
    float4 r;
    r.x = (x0 + x1) * inv; r.y = (y0 + y1) * inv;
    r.z = (z0 + z1) * inv; r.w = (w0 + w1) * inv;
    *(float4*)(g_A + (size_t)tok*(NH*KL) + h*KL) = r;
}

// ============ Kernel 4: out = A @ M + (bo + sum_h Mb), zero-MOV B operands ==
// 256(tok) x 64(j) tile, 256 thr, 16x4 microtile. B operands arrive
// pre-duplicated from g_MP/g_MQ via conflict-free LDS.128 -> no pack MOVs.
__global__ __launch_bounds__(256) void final_kernel(
    float* __restrict__ out, const float* __restrict__ bo)
{
    __shared__ __align__(16) float Ast[32][258];   // [k][row]
    __shared__ __align__(16) float BsP[32][64];    // [k][16 quads x {c0,c0,c1,c1}]
    __shared__ __align__(16) float BsQ[32][64];    // [k][16 quads x {c2,c2,c3,c3}]
    const int tok0 = blockIdx.y * 256, j0 = blockIdx.x * 64;
    const int tid = threadIdx.x;
    const int tx = tid & 15, ty = tid >> 4;

    u64 acc[8][4];
    #pragma unroll
    for (int i = 0; i < 8; ++i)
        #pragma unroll
        for (int j = 0; j < 4; ++j) acc[i][j] = 0ull;

    for (int k0 = 0; k0 < NH*KL; k0 += 32) {
        // A: 256 rows x 32 k, transposed into Ast[k][r]
        #pragma unroll
        for (int s = 0; s < 8; ++s) {
            int i = tid + s*256;          // 0..2047
            int r = i >> 3, kq = (i & 7) * 4;
            float4 v = *(const float4*)&g_A[(size_t)(tok0 + r)*(NH*KL) + k0 + kq];
            Ast[kq+0][r] = v.x; Ast[kq+1][r] = v.y;
            Ast[kq+2][r] = v.z; Ast[kq+3][r] = v.w;
        }
        // B: 32 k x 64 floats per array (duplicated layout)
        #pragma unroll
        for (int s = 0; s < 2; ++s) {
            int i = tid + s*256;          // 0..511
            int k = i >> 4, jq = (i & 15) * 4;
            *(float4*)&BsP[k][jq] = *(const float4*)&g_MP[(size_t)(k0 + k)*DM + j0 + jq];
            *(float4*)&BsQ[k][jq] = *(const float4*)&g_MQ[(size_t)(k0 + k)*DM + j0 + jq];
        }
        __syncthreads();
        #pragma unroll 2
        for (int k = 0; k < 32; ++k) {
            ulonglong2 bp = *(const ulonglong2*)&BsP[k][tx*4];
            ulonglong2 bq = *(const ulonglong2*)&BsQ[k][tx*4];
            #pragma unroll
            for (int i = 0; i < 8; ++i) {
                u64 a = *(const u64*)&Ast[k][ty*2 + 32*i];
                acc[i][0] = f2fma(a, bp.x, acc[i][0]);
                acc[i][1] = f2fma(a, bp.y, acc[i][1]);
                acc[i][2] = f2fma(a, bq.x, acc[i][2]);
                acc[i][3] = f2fma(a, bq.y, acc[i][3]);
            }
        }
        __syncthreads();
    }

    // effective bias for this thread's 4 columns: bo + sum_h Mb[h]
    float4 bj = *(const float4*)&bo[j0 + tx*4];
    #pragma unroll
    for (int h = 0; h < NH; ++h) {
        float4 m = *(const float4*)&g_Mb[(size_t)h*DM + j0 + tx*4];
        bj.x += m.x; bj.y += m.y; bj.z += m.z; bj.w += m.w;
    }

    #pragma unroll
    for (int i = 0; i < 8; ++i) {
        float lo0, hi0, lo1, hi1, lo2, hi2, lo3, hi3;
        f2unpack(acc[i][0], lo0, hi0);
        f2unpack(acc[i][1], lo1, hi1);
        f2unpack(acc[i][2], lo2, hi2);
        f2unpack(acc[i][3], lo3, hi3);
        float4 ra, rb;
        ra.x = lo0 + bj.x; ra.y = lo1 + bj.y; ra.z = lo2 + bj.z; ra.w = lo3 + bj.w;
        rb.x = hi0 + bj.x; rb.y = hi1 + bj.y; rb.z = hi2 + bj.z; rb.w = hi3 + bj.w;
        size_t row = (size_t)(tok0 + ty*2 + 32*i);
        *(float4*)&out[row*DM + j0 + tx*4]       = ra;
        *(float4*)&out[(row + 1)*DM + j0 + tx*4] = rb;
    }
}

// ============================================================================
extern "C" void kernel_launch(void* const* d_in, const int* in_sizes, int n_in,
                              void* d_out, int out_size)
{
    const float* x    = (const float*)d_in[0];
    const float* Wq_d = (const float*)d_in[1];
    const float* bq_d = (const float*)d_in[2];
    const float* W_qk = (const float*)d_in[3];
    const float* b_qk = (const float*)d_in[4];
    const float* Wkv_d= (const float*)d_in[5];
    const float* bkv_d= (const float*)d_in[6];
    const float* Wv_u = (const float*)d_in[7];
    const float* bv_u = (const float*)d_in[8];
    const float* Wo   = (const float*)d_in[9];
    const float* bo   = (const float*)d_in[10];
    float* out = (float*)d_out;

    proj_kernel<<<NT/32, 512>>>(x, Wq_d, bq_d, W_qk, b_qk, Wkv_d, bkv_d);
    precM_kernel<<<dim3(DM/256, NH), 256>>>(Wv_u, Wo, bv_u);
    attn_kernel<<<dim3(SS/128, NH, BB), 128>>>();
    final_kernel<<<dim3(DM/64, NT/256), 256>>>(out, bo);
}

// round 7
// speedup vs baseline: 1.0026x; 1.0026x over previous
#include <cuda_runtime.h>

#define BB 2
#define SS 2048
#define DM 4096
#define NH 32
#define HD 128
#define QL 12
#define KL 4
#define NT (BB*SS)   // 4096 tokens

typedef unsigned long long u64;

// ---------------- f32x2 packed-math helpers (sm_103a) ----------------------
__device__ __forceinline__ u64 f2pack(float lo, float hi) {
    u64 r; asm("mov.b64 %0, {%1, %2};" : "=l"(r) : "f"(lo), "f"(hi)); return r;
}
__device__ __forceinline__ void f2unpack(u64 v, float& lo, float& hi) {
    asm("mov.b64 {%0, %1}, %2;" : "=f"(lo), "=f"(hi) : "l"(v));
}
__device__ __forceinline__ u64 f2fma(u64 a, u64 b, u64 c) {
    u64 d; asm("fma.rn.f32x2 %0, %1, %2, %3;" : "=l"(d) : "l"(a), "l"(b), "l"(c)); return d;
}
__device__ __forceinline__ u64 f2mul(u64 a, u64 b) {
    u64 d; asm("mul.rn.f32x2 %0, %1, %2;" : "=l"(d) : "l"(a), "l"(b)); return d;
}
__device__ __forceinline__ u64 f2add(u64 a, u64 b) {
    u64 d; asm("add.rn.f32x2 %0, %1, %2;" : "=l"(d) : "l"(a), "l"(b)); return d;
}
__device__ __forceinline__ float ex2f(float x) {
    float y; asm("ex2.approx.f32 %0, %1;" : "=f"(y) : "f"(x)); return y;
}

// ---------------- scratch (device globals; no allocations) ----------------
__device__ __align__(16) float g_Ckv[NT*KL];        // 64 KB
__device__ __align__(16) float g_q  [NT*NH*KL];     // 2 MB  (pre-scaled by 0.5*log2e)
__device__ __align__(16) float g_At [NH*KL*NT];     // 2 MB  (attended latent, TRANSPOSED [k][tok])
__device__ __align__(16) float g_M  [NH*KL*DM];     // 2 MB
__device__ __align__(16) float g_Mb [NH*DM];        // 512 KB

#define QSCALE 0.7213475204444817f   /* 0.5 * log2(e) */

// ============ Kernel 1: x -> C_q, C_kv, q (float4 x-fill) ===================
__global__ __launch_bounds__(512) void proj_kernel(
    const float* __restrict__ x,   const float* __restrict__ Wq,
    const float* __restrict__ bq,  const float* __restrict__ Wqk,
    const float* __restrict__ bqk, const float* __restrict__ Wkv,
    const float* __restrict__ bkv)
{
    __shared__ __align__(16) float xs[32][128];
    __shared__ __align__(16) float ws[16][132];
    __shared__ float cq[32][16];

    const int tid  = threadIdx.x;
    const int tok0 = blockIdx.x * 32;
    const int tok  = tid >> 4;
    const int c    = tid & 15;

    u64 acc2 = 0ull;
    for (int d0 = 0; d0 < DM; d0 += 128) {
        #pragma unroll
        for (int s = 0; s < 2; ++s) {
            int i = tid + s*512;          // 0..1023 float4 slots
            int t = i >> 5, q = (i & 31) * 4;
            *(float4*)&xs[t][q] = *(const float4*)&x[(size_t)(tok0 + t)*DM + d0 + q];
        }
        #pragma unroll
        for (int i = tid; i < 16*128; i += 512) {
            int d = i >> 4, cc = i & 15;
            ws[cc][d] = (cc < QL) ? Wq[(size_t)(d0+d)*QL + cc]
                                  : Wkv[(size_t)(d0+d)*KL + (cc-QL)];
        }
        __syncthreads();
        #pragma unroll 8
        for (int d = 0; d < 128; d += 4) {
            ulonglong2 xv = *(const ulonglong2*)&xs[tok][d];
            ulonglong2 wv = *(const ulonglong2*)&ws[c][d];
            acc2 = f2fma(xv.x, wv.x, acc2);
            acc2 = f2fma(xv.y, wv.y, acc2);
        }
        __syncthreads();
    }
    float alo, ahi; f2unpack(acc2, alo, ahi);
    float biased = (alo + ahi) + ((c < QL) ? bq[c] : bkv[c - QL]);
    cq[tok][c] = biased;
    if (c >= QL) g_Ckv[(size_t)(tok0 + tok)*KL + (c - QL)] = biased;
    __syncthreads();

    float cql[QL];
    #pragma unroll
    for (int i = 0; i < QL; ++i) cql[i] = cq[tok][i];
    const int o0 = c * 8;
    #pragma unroll
    for (int oo = 0; oo < 8; ++oo) {
        int o = o0 + oo;
        float s = bqk[o];
        #pragma unroll
        for (int i = 0; i < QL; ++i) s = fmaf(cql[i], Wqk[i*(NH*KL) + o], s);
        g_q[(size_t)(tok0 + tok)*(NH*KL) + o] = QSCALE * s;
    }
}

// ============ Kernel 2: fold Wv_u into Wo (float4-j, single wave) ===========
__global__ __launch_bounds__(256) void precM_kernel(
    const float* __restrict__ Wvu, const float* __restrict__ Wo,
    const float* __restrict__ bvu)
{
    __shared__ float vu[KL][HD];
    __shared__ float bvs[HD];
    const int h = blockIdx.y;
    const int j = (blockIdx.x * 256 + threadIdx.x) * 4;
    for (int i = threadIdx.x; i < KL*HD; i += 256) {
        int k = i >> 7, d = i & 127;
        vu[k][d] = Wvu[(size_t)k*(NH*HD) + h*HD + d];
    }
    if (threadIdx.x < HD) bvs[threadIdx.x] = bvu[h*HD + threadIdx.x];
    __syncthreads();

    float4 a0 = {0,0,0,0}, a1 = a0, a2 = a0, a3 = a0, ab = a0;
    #pragma unroll 4
    for (int d = 0; d < HD; ++d) {
        float4 w = *(const float4*)&Wo[(size_t)(h*HD + d)*DM + j];
        float v0 = vu[0][d], v1 = vu[1][d], v2 = vu[2][d], v3 = vu[3][d], vb = bvs[d];
        a0.x=fmaf(v0,w.x,a0.x); a0.y=fmaf(v0,w.y,a0.y); a0.z=fmaf(v0,w.z,a0.z); a0.w=fmaf(v0,w.w,a0.w);
        a1.x=fmaf(v1,w.x,a1.x); a1.y=fmaf(v1,w.y,a1.y); a1.z=fmaf(v1,w.z,a1.z); a1.w=fmaf(v1,w.w,a1.w);
        a2.x=fmaf(v2,w.x,a2.x); a2.y=fmaf(v2,w.y,a2.y); a2.z=fmaf(v2,w.z,a2.z); a2.w=fmaf(v2,w.w,a2.w);
        a3.x=fmaf(v3,w.x,a3.x); a3.y=fmaf(v3,w.y,a3.y); a3.z=fmaf(v3,w.z,a3.z); a3.w=fmaf(v3,w.w,a3.w);
        ab.x=fmaf(vb,w.x,ab.x); ab.y=fmaf(vb,w.y,ab.y); ab.z=fmaf(vb,w.z,ab.z); ab.w=fmaf(vb,w.w,ab.w);
    }
    *(float4*)&g_M[(size_t)(h*KL + 0)*DM + j] = a0;
    *(float4*)&g_M[(size_t)(h*KL + 1)*DM + j] = a1;
    *(float4*)&g_M[(size_t)(h*KL + 2)*DM + j] = a2;
    *(float4*)&g_M[(size_t)(h*KL + 3)*DM + j] = a3;
    *(float4*)&g_Mb[(size_t)h*DM + j] = ab;
}

// ============ Kernel 3: latent attention (round-5 body, transposed store) ===
__global__ __launch_bounds__(128) void attn_kernel()
{
    __shared__ __align__(16) float ckx[SS];
    __shared__ __align__(16) float cky[SS];
    __shared__ __align__(16) float ckz[SS];
    __shared__ __align__(16) float ckw[SS];
    const int b = blockIdx.z, h = blockIdx.y;
    const float4* ckv = (const float4*)(g_Ckv + (size_t)b*SS*KL);
    for (int i = threadIdx.x; i < SS; i += 128) {
        float4 v = ckv[i];
        ckx[i] = v.x; cky[i] = v.y; ckz[i] = v.z; ckw[i] = v.w;
    }
    __syncthreads();

    const int tok = b*SS + blockIdx.x*128 + threadIdx.x;
    const float4 qv = *(const float4*)(g_q + (size_t)tok*(NH*KL) + h*KL);
    const u64 qx2 = f2pack(qv.x, qv.x);
    const u64 qy2 = f2pack(qv.y, qv.y);
    const u64 qz2 = f2pack(qv.z, qv.z);
    const u64 qw2 = f2pack(qv.w, qv.w);

    const ulonglong2* cxp = (const ulonglong2*)ckx;
    const ulonglong2* cyp = (const ulonglong2*)cky;
    const ulonglong2* czp = (const ulonglong2*)ckz;
    const ulonglong2* cwp = (const ulonglong2*)ckw;

    u64 lA=0ull, axA=0ull, ayA=0ull, azA=0ull, awA=0ull;
    u64 lB=0ull, axB=0ull, ayB=0ull, azB=0ull, awB=0ull;
    #pragma unroll 4
    for (int k = 0; k < SS/4; ++k) {
        ulonglong2 cx2 = cxp[k], cy2 = cyp[k], cz2 = czp[k], cw2 = cwp[k];
        u64 sa = f2mul(qx2, cx2.x);
        u64 sb = f2mul(qx2, cx2.y);
        sa = f2fma(qy2, cy2.x, sa);  sb = f2fma(qy2, cy2.y, sb);
        sa = f2fma(qz2, cz2.x, sa);  sb = f2fma(qz2, cz2.y, sb);
        sa = f2fma(qw2, cw2.x, sa);  sb = f2fma(qw2, cw2.y, sb);
        float s0,s1,s2,s3; f2unpack(sa, s0, s1); f2unpack(sb, s2, s3);
        u64 ea = f2pack(ex2f(s0), ex2f(s1));
        u64 eb = f2pack(ex2f(s2), ex2f(s3));
        lA  = f2add(lA, ea);             lB  = f2add(lB, eb);
        axA = f2fma(ea, cx2.x, axA);     axB = f2fma(eb, cx2.y, axB);
        ayA = f2fma(ea, cy2.x, ayA);     ayB = f2fma(eb, cy2.y, ayB);
        azA = f2fma(ea, cz2.x, azA);     azB = f2fma(eb, cz2.y, azB);
        awA = f2fma(ea, cw2.x, awA);     awB = f2fma(eb, cw2.y, awB);
    }
    u64 l2  = f2add(lA, lB);
    u64 ax2 = f2add(axA, axB), ay2 = f2add(ayA, ayB);
    u64 az2 = f2add(azA, azB), aw2 = f2add(awA, awB);
    float l0,l1,x0,x1,y0,y1,z0,z1,w0,w1;
    f2unpack(l2, l0, l1);
    f2unpack(ax2, x0, x1); f2unpack(ay2, y0, y1);
    f2unpack(az2, z0, z1); f2unpack(aw2, w0, w1);
    float inv = 1.f / (l0 + l1);
    // transposed store: g_At[k][tok], k = h*4 + l  (coalesced across threads)
    const int kbase = h * KL;
    g_At[(size_t)(kbase + 0)*NT + tok] = (x0 + x1) * inv;
    g_At[(size_t)(kbase + 1)*NT + tok] = (y0 + y1) * inv;
    g_At[(size_t)(kbase + 2)*NT + tok] = (z0 + z1) * inv;
    g_At[(size_t)(kbase + 3)*NT + tok] = (w0 + w1) * inv;
}

// ============ Kernel 4: out = A @ M + (bo + sum_h Mb) =======================
// round-5 body; A fill is now direct LDG.128 -> STS.128 from pre-transposed g_At.
__global__ __launch_bounds__(256) void final_kernel(
    float* __restrict__ out, const float* __restrict__ bo)
{
    __shared__ __align__(16) float Ast[32][260];   // [k][row], stride 260 (16B-aligned)
    __shared__ __align__(16) float Bs[32][68];     // [k][j]
    const int tok0 = blockIdx.y * 256, j0 = blockIdx.x * 64;
    const int tid = threadIdx.x;
    const int tx = tid & 15, ty = tid >> 4;

    u64 acc[8][4];
    #pragma unroll
    for (int i = 0; i < 8; ++i)
        #pragma unroll
        for (int j = 0; j < 4; ++j) acc[i][j] = 0ull;

    for (int k0 = 0; k0 < NH*KL; k0 += 32) {
        // A: 32 k-rows x 256 tok, direct vector copy (no transpose needed)
        #pragma unroll
        for (int s = 0; s < 8; ++s) {
            int i = tid + s*256;          // 0..2047 float4 slots
            int k = i >> 6, rq = (i & 63) * 4;
            *(float4*)&Ast[k][rq] =
                *(const float4*)&g_At[(size_t)(k0 + k)*NT + tok0 + rq];
        }
        // B: 32 k x 64 j
        #pragma unroll
        for (int s = 0; s < 2; ++s) {
            int i = tid + s*256;          // 0..511
            int k = i >> 4, jq = (i & 15) * 4;
            *(float4*)&Bs[k][jq] = *(const float4*)&g_M[(size_t)(k0 + k)*DM + j0 + jq];
        }
        __syncthreads();
        #pragma unroll 2
        for (int k = 0; k < 32; ++k) {
            float4 bv = *(const float4*)&Bs[k][tx*4];
            u64 b0 = f2pack(bv.x, bv.x);
            u64 b1 = f2pack(bv.y, bv.y);
            u64 b2 = f2pack(bv.z, bv.z);
            u64 b3 = f2pack(bv.w, bv.w);
            #pragma unroll
            for (int i = 0; i < 8; ++i) {
                u64 a = *(const u64*)&Ast[k][ty*2 + 32*i];
                acc[i][0] = f2fma(a, b0, acc[i][0]);
                acc[i][1] = f2fma(a, b1, acc[i][1]);
                acc[i][2] = f2fma(a, b2, acc[i][2]);
                acc[i][3] = f2fma(a, b3, acc[i][3]);
            }
        }
        __syncthreads();
    }

    // effective bias for this thread's 4 columns: bo + sum_h Mb[h]
    float4 bj = *(const float4*)&bo[j0 + tx*4];
    #pragma unroll
    for (int h = 0; h < NH; ++h) {
        float4 m = *(const float4*)&g_Mb[(size_t)h*DM + j0 + tx*4];
        bj.x += m.x; bj.y += m.y; bj.z += m.z; bj.w += m.w;
    }

    #pragma unroll
    for (int i = 0; i < 8; ++i) {
        float lo0, hi0, lo1, hi1, lo2, hi2, lo3, hi3;
        f2unpack(acc[i][0], lo0, hi0);
        f2unpack(acc[i][1], lo1, hi1);
        f2unpack(acc[i][2], lo2, hi2);
        f2unpack(acc[i][3], lo3, hi3);
        float4 ra, rb;
        ra.x = lo0 + bj.x; ra.y = lo1 + bj.y; ra.z = lo2 + bj.z; ra.w = lo3 + bj.w;
        rb.x = hi0 + bj.x; rb.y = hi1 + bj.y; rb.z = hi2 + bj.z; rb.w = hi3 + bj.w;
        size_t row = (size_t)(tok0 + ty*2 + 32*i);
        *(float4*)&out[row*DM + j0 + tx*4]       = ra;
        *(float4*)&out[(row + 1)*DM + j0 + tx*4] = rb;
    }
}

// ============================================================================
extern "C" void kernel_launch(void* const* d_in, const int* in_sizes, int n_in,
                              void* d_out, int out_size)
{
    const float* x    = (const float*)d_in[0];
    const float* Wq_d = (const float*)d_in[1];
    const float* bq_d = (const float*)d_in[2];
    const float* W_qk = (const float*)d_in[3];
    const float* b_qk = (const float*)d_in[4];
    const float* Wkv_d= (const float*)d_in[5];
    const float* bkv_d= (const float*)d_in[6];
    const float* Wv_u = (const float*)d_in[7];
    const float* bv_u = (const float*)d_in[8];
    const float* Wo   = (const float*)d_in[9];
    const float* bo   = (const float*)d_in[10];
    float* out = (float*)d_out;

    proj_kernel<<<NT/32, 512>>>(x, Wq_d, bq_d, W_qk, b_qk, Wkv_d, bkv_d);
    precM_kernel<<<dim3(DM/1024, NH), 256>>>(Wv_u, Wo, bv_u);
    attn_kernel<<<dim3(SS/128, NH, BB), 128>>>();
    final_kernel<<<dim3(DM/64, NT/256), 256>>>(out, bo);
}

// round 8
// speedup vs baseline: 1.0418x; 1.0391x over previous
#include <cuda_runtime.h>

#define BB 2
#define SS 2048
#define DM 4096
#define NH 32
#define HD 128
#define QL 12
#define KL 4
#define NT (BB*SS)   // 4096 tokens

typedef unsigned long long u64;

// ---------------- f32x2 packed-math helpers (sm_103a) ----------------------
__device__ __forceinline__ u64 f2pack(float lo, float hi) {
    u64 r; asm("mov.b64 %0, {%1, %2};" : "=l"(r) : "f"(lo), "f"(hi)); return r;
}
__device__ __forceinline__ void f2unpack(u64 v, float& lo, float& hi) {
    asm("mov.b64 {%0, %1}, %2;" : "=f"(lo), "=f"(hi) : "l"(v));
}
__device__ __forceinline__ u64 f2fma(u64 a, u64 b, u64 c) {
    u64 d; asm("fma.rn.f32x2 %0, %1, %2, %3;" : "=l"(d) : "l"(a), "l"(b), "l"(c)); return d;
}
__device__ __forceinline__ u64 f2mul(u64 a, u64 b) {
    u64 d; asm("mul.rn.f32x2 %0, %1, %2;" : "=l"(d) : "l"(a), "l"(b)); return d;
}
__device__ __forceinline__ u64 f2add(u64 a, u64 b) {
    u64 d; asm("add.rn.f32x2 %0, %1, %2;" : "=l"(d) : "l"(a), "l"(b)); return d;
}
__device__ __forceinline__ float ex2f(float x) {
    float y; asm("ex2.approx.f32 %0, %1;" : "=f"(y) : "f"(x)); return y;
}

// ---------------- scratch (device globals; no allocations) ----------------
__device__ __align__(16) float g_Ckv[NT*KL];        // 64 KB
__device__ __align__(16) float g_q  [NT*NH*KL];     // 2 MB  (pre-scaled by 0.5*log2e)
__device__ __align__(16) float g_A  [NT*NH*KL];     // 2 MB
__device__ __align__(16) float g_M  [NH*KL*DM];     // 2 MB
__device__ __align__(16) float g_Mb [NH*DM];        // 512 KB

#define QSCALE 0.7213475204444817f   /* 0.5 * log2(e) */

// ============ Kernel 1: x -> C_q, C_kv, q (round-5 known-good) ==============
__global__ __launch_bounds__(512) void proj_kernel(
    const float* __restrict__ x,   const float* __restrict__ Wq,
    const float* __restrict__ bq,  const float* __restrict__ Wqk,
    const float* __restrict__ bqk, const float* __restrict__ Wkv,
    const float* __restrict__ bkv)
{
    __shared__ __align__(16) float xs[32][128];
    __shared__ __align__(16) float ws[16][132];
    __shared__ float cq[32][16];

    const int tid  = threadIdx.x;
    const int tok0 = blockIdx.x * 32;
    const int tok  = tid >> 4;
    const int c    = tid & 15;

    u64 acc2 = 0ull;
    for (int d0 = 0; d0 < DM; d0 += 128) {
        #pragma unroll
        for (int i = tid; i < 32*128; i += 512) {
            int t = i >> 7, d = i & 127;
            xs[t][d] = x[(size_t)(tok0 + t)*DM + d0 + d];
        }
        #pragma unroll
        for (int i = tid; i < 16*128; i += 512) {
            int d = i >> 4, cc = i & 15;
            ws[cc][d] = (cc < QL) ? Wq[(size_t)(d0+d)*QL + cc]
                                  : Wkv[(size_t)(d0+d)*KL + (cc-QL)];
        }
        __syncthreads();
        #pragma unroll 8
        for (int d = 0; d < 128; d += 4) {
            ulonglong2 xv = *(const ulonglong2*)&xs[tok][d];
            ulonglong2 wv = *(const ulonglong2*)&ws[c][d];
            acc2 = f2fma(xv.x, wv.x, acc2);
            acc2 = f2fma(xv.y, wv.y, acc2);
        }
        __syncthreads();
    }
    float alo, ahi; f2unpack(acc2, alo, ahi);
    float biased = (alo + ahi) + ((c < QL) ? bq[c] : bkv[c - QL]);
    cq[tok][c] = biased;
    if (c >= QL) g_Ckv[(size_t)(tok0 + tok)*KL + (c - QL)] = biased;
    __syncthreads();

    float cql[QL];
    #pragma unroll
    for (int i = 0; i < QL; ++i) cql[i] = cq[tok][i];
    const int o0 = c * 8;
    #pragma unroll
    for (int oo = 0; oo < 8; ++oo) {
        int o = o0 + oo;
        float s = bqk[o];
        #pragma unroll
        for (int i = 0; i < QL; ++i) s = fmaf(cql[i], Wqk[i*(NH*KL) + o], s);
        g_q[(size_t)(tok0 + tok)*(NH*KL) + o] = QSCALE * s;
    }
}

// ============ Kernel 2: fold Wv_u into Wo (round-5 known-good) ==============
__global__ __launch_bounds__(256) void precM_kernel(
    const float* __restrict__ Wvu, const float* __restrict__ Wo,
    const float* __restrict__ bvu)
{
    __shared__ float vu[KL][HD];
    __shared__ float bvs[HD];
    const int h = blockIdx.y;
    const int j = blockIdx.x * 256 + threadIdx.x;
    for (int i = threadIdx.x; i < KL*HD; i += 256) {
        int k = i >> 7, d = i & 127;
        vu[k][d] = Wvu[(size_t)k*(NH*HD) + h*HD + d];
    }
    if (threadIdx.x < HD) bvs[threadIdx.x] = bvu[h*HD + threadIdx.x];
    __syncthreads();

    float a0=0.f, a1=0.f, a2=0.f, a3=0.f, ab=0.f;
    #pragma unroll 4
    for (int d = 0; d < HD; ++d) {
        float w = Wo[(size_t)(h*HD + d)*DM + j];
        a0 = fmaf(vu[0][d], w, a0);
        a1 = fmaf(vu[1][d], w, a1);
        a2 = fmaf(vu[2][d], w, a2);
        a3 = fmaf(vu[3][d], w, a3);
        ab = fmaf(bvs[d],   w, ab);
    }
    g_M[(size_t)(h*KL + 0)*DM + j] = a0;
    g_M[(size_t)(h*KL + 1)*DM + j] = a1;
    g_M[(size_t)(h*KL + 2)*DM + j] = a2;
    g_M[(size_t)(h*KL + 3)*DM + j] = a3;
    g_Mb[(size_t)h*DM + j] = ab;
}

// ============ Kernel 3: latent attention — query-blocked, broadcast keys ====
// grid (4 q-tiles, 32 heads, 2 batch) x 128 thr; 4 queries/thread.
// One broadcast LDS.128 per key serves 4 queries -> 4x less SMEM traffic.
// f32x2 packs query PAIRS; key components duplicated via alu packs.
__global__ __launch_bounds__(128) void attn_kernel()
{
    __shared__ __align__(16) float4 ck[SS];   // 32 KB, AoS
    const int b = blockIdx.z, h = blockIdx.y;
    const float4* ckv = (const float4*)(g_Ckv + (size_t)b*SS*KL);
    for (int i = threadIdx.x; i < SS; i += 128) ck[i] = ckv[i];
    __syncthreads();

    const int tok0 = b*SS + blockIdx.x*512 + threadIdx.x;
    const float4 q0 = *(const float4*)(g_q + (size_t)(tok0      )*(NH*KL) + h*KL);
    const float4 q1 = *(const float4*)(g_q + (size_t)(tok0 + 128)*(NH*KL) + h*KL);
    const float4 q2 = *(const float4*)(g_q + (size_t)(tok0 + 256)*(NH*KL) + h*KL);
    const float4 q3 = *(const float4*)(g_q + (size_t)(tok0 + 384)*(NH*KL) + h*KL);
    const u64 qxA = f2pack(q0.x, q1.x), qyA = f2pack(q0.y, q1.y);
    const u64 qzA = f2pack(q0.z, q1.z), qwA = f2pack(q0.w, q1.w);
    const u64 qxB = f2pack(q2.x, q3.x), qyB = f2pack(q2.y, q3.y);
    const u64 qzB = f2pack(q2.z, q3.z), qwB = f2pack(q2.w, q3.w);

    u64 lA=0ull, axA=0ull, ayA=0ull, azA=0ull, awA=0ull;
    u64 lB=0ull, axB=0ull, ayB=0ull, azB=0ull, awB=0ull;
    #pragma unroll 4
    for (int k = 0; k < SS; ++k) {
        float4 c = ck[k];                       // broadcast LDS.128
        u64 cx2 = f2pack(c.x, c.x);
        u64 cy2 = f2pack(c.y, c.y);
        u64 cz2 = f2pack(c.z, c.z);
        u64 cw2 = f2pack(c.w, c.w);
        u64 sA = f2mul(qxA, cx2);    u64 sB = f2mul(qxB, cx2);
        sA = f2fma(qyA, cy2, sA);    sB = f2fma(qyB, cy2, sB);
        sA = f2fma(qzA, cz2, sA);    sB = f2fma(qzB, cz2, sB);
        sA = f2fma(qwA, cw2, sA);    sB = f2fma(qwB, cw2, sB);
        float s0,s1,s2,s3; f2unpack(sA, s0, s1); f2unpack(sB, s2, s3);
        u64 eA = f2pack(ex2f(s0), ex2f(s1));
        u64 eB = f2pack(ex2f(s2), ex2f(s3));
        lA  = f2add(lA, eA);         lB  = f2add(lB, eB);
        axA = f2fma(eA, cx2, axA);   axB = f2fma(eB, cx2, axB);
        ayA = f2fma(eA, cy2, ayA);   ayB = f2fma(eB, cy2, ayB);
        azA = f2fma(eA, cz2, azA);   azB = f2fma(eB, cz2, azB);
        awA = f2fma(eA, cw2, awA);   awB = f2fma(eB, cw2, awB);
    }
    float v0,v1,w0,w1;
    float4 r;
    // queries q0,q1 from the A set
    f2unpack(lA, v0, v1);
    {
        float inv0 = 1.f / v0, inv1 = 1.f / v1;
        f2unpack(axA, v0, w0); f2unpack(ayA, v1, w1);
        float az0,az1,aw0,aw1; f2unpack(azA, az0, az1); f2unpack(awA, aw0, aw1);
        r.x = v0*inv0; r.y = v1*inv0; r.z = az0*inv0; r.w = aw0*inv0;
        *(float4*)(g_A + (size_t)(tok0      )*(NH*KL) + h*KL) = r;
        r.x = w0*inv1; r.y = w1*inv1; r.z = az1*inv1; r.w = aw1*inv1;
        *(float4*)(g_A + (size_t)(tok0 + 128)*(NH*KL) + h*KL) = r;
    }
    // queries q2,q3 from the B set
    f2unpack(lB, v0, v1);
    {
        float inv2 = 1.f / v0, inv3 = 1.f / v1;
        f2unpack(axB, v0, w0); f2unpack(ayB, v1, w1);
        float az0,az1,aw0,aw1; f2unpack(azB, az0, az1); f2unpack(awB, aw0, aw1);
        r.x = v0*inv2; r.y = v1*inv2; r.z = az0*inv2; r.w = aw0*inv2;
        *(float4*)(g_A + (size_t)(tok0 + 256)*(NH*KL) + h*KL) = r;
        r.x = w0*inv3; r.y = w1*inv3; r.z = az1*inv3; r.w = aw1*inv3;
        *(float4*)(g_A + (size_t)(tok0 + 384)*(NH*KL) + h*KL) = r;
    }
}

// ============ Kernel 4: out = A @ M + (bo + sum_h Mb) (round-5 known-good) ==
__global__ __launch_bounds__(256) void final_kernel(
    float* __restrict__ out, const float* __restrict__ bo)
{
    __shared__ __align__(16) float Ast[32][258];   // [k][row], stride 258
    __shared__ __align__(16) float Bs[32][68];     // [k][j]
    const int tok0 = blockIdx.y * 256, j0 = blockIdx.x * 64;
    const int tid = threadIdx.x;
    const int tx = tid & 15, ty = tid >> 4;

    u64 acc[8][4];
    #pragma unroll
    for (int i = 0; i < 8; ++i)
        #pragma unroll
        for (int j = 0; j < 4; ++j) acc[i][j] = 0ull;

    for (int k0 = 0; k0 < NH*KL; k0 += 32) {
        #pragma unroll
        for (int s = 0; s < 8; ++s) {
            int i = tid + s*256;          // 0..2047
            int r = i >> 3, kq = (i & 7) * 4;
            float4 v = *(const float4*)&g_A[(size_t)(tok0 + r)*(NH*KL) + k0 + kq];
            Ast[kq+0][r] = v.x; Ast[kq+1][r] = v.y;
            Ast[kq+2][r] = v.z; Ast[kq+3][r] = v.w;
        }
        #pragma unroll
        for (int s = 0; s < 2; ++s) {
            int i = tid + s*256;          // 0..511
            int k = i >> 4, jq = (i & 15) * 4;
            *(float4*)&Bs[k][jq] = *(const float4*)&g_M[(size_t)(k0 + k)*DM + j0 + jq];
        }
        __syncthreads();
        #pragma unroll 2
        for (int k = 0; k < 32; ++k) {
            float4 bv = *(const float4*)&Bs[k][tx*4];
            u64 b0 = f2pack(bv.x, bv.x);
            u64 b1 = f2pack(bv.y, bv.y);
            u64 b2 = f2pack(bv.z, bv.z);
            u64 b3 = f2pack(bv.w, bv.w);
            #pragma unroll
            for (int i = 0; i < 8; ++i) {
                u64 a = *(const u64*)&Ast[k][ty*2 + 32*i];
                acc[i][0] = f2fma(a, b0, acc[i][0]);
                acc[i][1] = f2fma(a, b1, acc[i][1]);
                acc[i][2] = f2fma(a, b2, acc[i][2]);
                acc[i][3] = f2fma(a, b3, acc[i][3]);
            }
        }
        __syncthreads();
    }

    float4 bj = *(const float4*)&bo[j0 + tx*4];
    #pragma unroll
    for (int h = 0; h < NH; ++h) {
        float4 m = *(const float4*)&g_Mb[(size_t)h*DM + j0 + tx*4];
        bj.x += m.x; bj.y += m.y; bj.z += m.z; bj.w += m.w;
    }

    #pragma unroll
    for (int i = 0; i < 8; ++i) {
        float lo0, hi0, lo1, hi1, lo2, hi2, lo3, hi3;
        f2unpack(acc[i][0], lo0, hi0);
        f2unpack(acc[i][1], lo1, hi1);
        f2unpack(acc[i][2], lo2, hi2);
        f2unpack(acc[i][3], lo3, hi3);
        float4 ra, rb;
        ra.x = lo0 + bj.x; ra.y = lo1 + bj.y; ra.z = lo2 + bj.z; ra.w = lo3 + bj.w;
        rb.x = hi0 + bj.x; rb.y = hi1 + bj.y; rb.z = hi2 + bj.z; rb.w = hi3 + bj.w;
        size_t row = (size_t)(tok0 + ty*2 + 32*i);
        *(float4*)&out[row*DM + j0 + tx*4]       = ra;
        *(float4*)&out[(row + 1)*DM + j0 + tx*4] = rb;
    }
}

// ============================================================================
extern "C" void kernel_launch(void* const* d_in, const int* in_sizes, int n_in,
                              void* d_out, int out_size)
{
    const float* x    = (const float*)d_in[0];
    const float* Wq_d = (const float*)d_in[1];
    const float* bq_d = (const float*)d_in[2];
    const float* W_qk = (const float*)d_in[3];
    const float* b_qk = (const float*)d_in[4];
    const float* Wkv_d= (const float*)d_in[5];
    const float* bkv_d= (const float*)d_in[6];
    const float* Wv_u = (const float*)d_in[7];
    const float* bv_u = (const float*)d_in[8];
    const float* Wo   = (const float*)d_in[9];
    const float* bo   = (const float*)d_in[10];
    float* out = (float*)d_out;

    proj_kernel<<<NT/32, 512>>>(x, Wq_d, bq_d, W_qk, b_qk, Wkv_d, bkv_d);
    precM_kernel<<<dim3(DM/256, NH), 256>>>(Wv_u, Wo, bv_u);
    attn_kernel<<<dim3(SS/512, NH, BB), 128>>>();
    final_kernel<<<dim3(DM/64, NT/256), 256>>>(out, bo);
}